// round 3
// baseline (speedup 1.0000x reference)
#include <cuda_runtime.h>
#include <cuda_bf16.h>

#define NEG_INF (-1e10f)
#define INVLN2 1.4426950408889634f
#define LN2    0.6931471805599453f

// Problem constants
#define BB 32
#define TT 1000
#define HH 512
#define VV 2048
#define LL 100
#define SS 201
#define MROWS (BB*TT)          // 32000
#define MPAD  (MROWS + 64)     // padding for DP prefetch overrun
#define RING  16

// ---------------- static device scratch (no allocation allowed) ----------------
__device__ __align__(16) static __nv_bfloat16 g_X[MROWS * HH];        // eouts bf16
__device__ __align__(16) static __nv_bfloat16 g_W[VV * HH];           // W bf16
__device__ __align__(16) static __nv_bfloat16 g_Wlab[BB * 128 * HH];  // gathered label weights
__device__ __align__(16) static float         g_blab[BB * 128];       // gathered label bias
__device__ __align__(16) static float         g_sumexp[MPAD];         // per-row sum(exp(logit))
__device__ __align__(16) static float         g_lab[(size_t)MPAD * 128]; // label logits -> log2-probs

// ---------------- helpers ----------------
__device__ __forceinline__ unsigned smem_u32(const void* p) {
    return (unsigned)__cvta_generic_to_shared(p);
}

#define CP_ASYNC16(dst, src) \
    asm volatile("cp.async.ca.shared.global [%0], [%1], 16;\n" :: "r"(dst), "l"(src) : "memory")
#define CP_COMMIT() asm volatile("cp.async.commit_group;\n" ::: "memory")
#define CP_WAIT1()  asm volatile("cp.async.wait_group 1;\n" ::: "memory")

__device__ __forceinline__ void ldmatrix_x4(unsigned* r, unsigned addr) {
    asm volatile("ldmatrix.sync.aligned.m8n8.x4.shared.b16 {%0,%1,%2,%3}, [%4];\n"
                 : "=r"(r[0]), "=r"(r[1]), "=r"(r[2]), "=r"(r[3]) : "r"(addr));
}

__device__ __forceinline__ void mma_bf16(float* d, const unsigned* a, unsigned b0, unsigned b1) {
    asm volatile("mma.sync.aligned.m16n8k16.row.col.f32.bf16.bf16.f32 "
                 "{%0,%1,%2,%3}, {%4,%5,%6,%7}, {%8,%9}, {%0,%1,%2,%3};\n"
                 : "+f"(d[0]), "+f"(d[1]), "+f"(d[2]), "+f"(d[3])
                 : "r"(a[0]), "r"(a[1]), "r"(a[2]), "r"(a[3]), "r"(b0), "r"(b1));
}

__device__ __forceinline__ float ex2f(float x) {
    float y; asm("ex2.approx.f32 %0, %1;" : "=f"(y) : "f"(x)); return y;
}
__device__ __forceinline__ float lg2f(float x) {
    float y; asm("lg2.approx.f32 %0, %1;" : "=f"(y) : "f"(x)); return y;
}

// tag-stamped 16B boundary packet {tag, a30, a31, tag}: STS.128 is a single
// shared-memory transaction -> reader matching both tags gets a consistent packet.
__device__ __forceinline__ void st_bnd(unsigned addr, unsigned tag, float v30, float v31) {
    asm volatile("st.volatile.shared.v4.u32 [%0], {%1,%2,%3,%4};\n"
                 :: "r"(addr), "r"(tag), "r"(__float_as_uint(v30)),
                    "r"(__float_as_uint(v31)), "r"(tag) : "memory");
}
__device__ __forceinline__ uint4 ld_bnd(unsigned addr) {
    uint4 v;
    asm volatile("ld.volatile.shared.v4.u32 {%0,%1,%2,%3}, [%4];\n"
                 : "=r"(v.x), "=r"(v.y), "=r"(v.z), "=r"(v.w) : "r"(addr) : "memory");
    return v;
}

// ---------------- kernel 1: convert + gather + zero scratch/out ----------------
__global__ void prep_kernel(const float* __restrict__ eouts, const float* __restrict__ W,
                            const float* __restrict__ bias, const int* __restrict__ ys,
                            float* __restrict__ out, int out_size) {
    int i = blockIdx.x * blockDim.x + threadIdx.x;
    int stride = gridDim.x * blockDim.x;
    for (int k = i; k < MROWS * HH; k += stride) g_X[k] = __float2bfloat16(eouts[k]);
    for (int k = i; k < VV * HH; k += stride)    g_W[k] = __float2bfloat16(W[k]);
    for (int k = i; k < BB * 128 * HH; k += stride) {
        int kk = k & (HH - 1);
        int j  = (k >> 9) & 127;
        int b  = k >> 16;
        int v  = (j == 0) ? 0 : ((j <= LL) ? ys[b * LL + (j - 1)] : -1);
        g_Wlab[k] = (v >= 0) ? __float2bfloat16(W[(size_t)v * HH + kk]) : __float2bfloat16(0.0f);
    }
    for (int k = i; k < BB * 128; k += stride) {
        int j = k & 127;
        int b = k >> 7;
        int v = (j == 0) ? 0 : ((j <= LL) ? ys[b * LL + (j - 1)] : -1);
        g_blab[k] = (v >= 0) ? bias[v] : 0.0f;
    }
    for (int k = i; k < MPAD; k += stride) g_sumexp[k] = 0.0f;
    for (int k = i; k < out_size; k += stride) out[k] = 0.0f;
}

// ---------------- kernel 2: fused bf16 tensor-core GEMMs ----------------
// blocks [0, 4000):  full-V GEMM, epilogue reduces sum(exp(logit+bias)) -> atomicAdd g_sumexp
// blocks [4000, 4256): label GEMM per batch, epilogue stores logit+bias to g_lab
__global__ __launch_bounds__(256)
void gemm_fused_kernel(const float* __restrict__ bias) {
    __shared__ __nv_bfloat16 As[2][128 * 24];
    __shared__ __nv_bfloat16 Bs[2][128 * 24];

    const int flat = blockIdx.x;
    const bool mode0 = (flat < 4000);
    const int bx = mode0 ? (flat % 250) : ((flat - 4000) & 7);
    const int by = mode0 ? (flat / 250) : ((flat - 4000) >> 3);

    const int tid = threadIdx.x, lane = tid & 31, wid = tid >> 5;
    const int wm = (wid & 3) * 32;
    const int wn = (wid >> 2) * 64;

    const int ldrow = tid >> 1;
    const int ldcol = (tid & 1) * 8;

    const __nv_bfloat16* Ag;
    const __nv_bfloat16* Bg;
    int bb = 0;
    if (mode0) {
        Ag = g_X + (size_t)(bx * 128 + ldrow) * HH + ldcol;
        Bg = g_W + (size_t)(by * 128 + ldrow) * HH + ldcol;
    } else {
        bb = by;
        int t = bx * 128 + ldrow;
        if (t > TT - 1) t = TT - 1;  // clamp (values unused)
        Ag = g_X    + (size_t)(bb * TT + t) * HH + ldcol;
        Bg = g_Wlab + (size_t)(bb * 128 + ldrow) * HH + ldcol;
    }
    const int soff = ldrow * 24 + ldcol;

    float d[2][8][4];
#pragma unroll
    for (int mi = 0; mi < 2; mi++)
#pragma unroll
        for (int nj = 0; nj < 8; nj++)
#pragma unroll
            for (int q = 0; q < 4; q++) d[mi][nj][q] = 0.0f;

    unsigned aAddr[2], bAddr[4];
#pragma unroll
    for (int mi = 0; mi < 2; mi++)
        aAddr[mi] = smem_u32(&As[0][(wm + mi * 16 + (lane & 15)) * 24 + (lane >> 4) * 8]);
#pragma unroll
    for (int np = 0; np < 4; np++) {
        int r = wn + np * 16 + (lane & 7) + ((lane >> 4) & 1) * 8;
        int c = ((lane >> 3) & 1) * 8;
        bAddr[np] = smem_u32(&Bs[0][r * 24 + c]);
    }

    {
        CP_ASYNC16(smem_u32(&As[0][soff]), Ag + 0);
        CP_ASYNC16(smem_u32(&Bs[0][soff]), Bg + 0);
        CP_COMMIT();
        CP_ASYNC16(smem_u32(&As[1][soff]), Ag + 16);
        CP_ASYNC16(smem_u32(&Bs[1][soff]), Bg + 16);
        CP_COMMIT();
    }

    for (int kt = 0; kt < HH / 16; kt++) {
        CP_WAIT1();
        __syncthreads();
        const int buf = kt & 1;
        const unsigned off = buf * 6144u;

        unsigned ra[2][4], rb[4][4];
#pragma unroll
        for (int mi = 0; mi < 2; mi++) ldmatrix_x4(ra[mi], aAddr[mi] + off);
#pragma unroll
        for (int np = 0; np < 4; np++) ldmatrix_x4(rb[np], bAddr[np] + off);
        __syncthreads();

        if (kt + 2 < HH / 16) {
            int k0 = (kt + 2) * 16;
            CP_ASYNC16(smem_u32(&As[buf][soff]), Ag + k0);
            CP_ASYNC16(smem_u32(&Bs[buf][soff]), Bg + k0);
            CP_COMMIT();
        } else {
            CP_COMMIT();
        }

#pragma unroll
        for (int mi = 0; mi < 2; mi++)
#pragma unroll
            for (int nj = 0; nj < 8; nj++) {
                int np = nj >> 1;
                unsigned b0 = (nj & 1) ? rb[np][2] : rb[np][0];
                unsigned b1 = (nj & 1) ? rb[np][3] : rb[np][1];
                mma_bf16(d[mi][nj], ra[mi], b0, b1);
            }
    }

    // ---------------- epilogue ----------------
    if (mode0) {
#pragma unroll
        for (int mi = 0; mi < 2; mi++) {
            float se0 = 0.0f, se1 = 0.0f;
            int r = bx * 128 + wm + mi * 16 + (lane >> 2);
#pragma unroll
            for (int nj = 0; nj < 8; nj++) {
                int c = by * 128 + wn + nj * 8 + (lane & 3) * 2;
                float b0 = __ldg(&bias[c]);
                float b1 = __ldg(&bias[c + 1]);
                se0 += __expf(d[mi][nj][0] + b0) + __expf(d[mi][nj][1] + b1);
                se1 += __expf(d[mi][nj][2] + b0) + __expf(d[mi][nj][3] + b1);
            }
            se0 += __shfl_xor_sync(0xffffffffu, se0, 1);
            se0 += __shfl_xor_sync(0xffffffffu, se0, 2);
            se1 += __shfl_xor_sync(0xffffffffu, se1, 1);
            se1 += __shfl_xor_sync(0xffffffffu, se1, 2);
            if ((lane & 3) == 0) {
                atomicAdd(&g_sumexp[r], se0);
                atomicAdd(&g_sumexp[r + 8], se1);
            }
        }
    } else {
#pragma unroll
        for (int mi = 0; mi < 2; mi++) {
            int trow = bx * 128 + wm + mi * 16 + (lane >> 2);
#pragma unroll
            for (int nj = 0; nj < 8; nj++) {
                int c = wn + nj * 8 + (lane & 3) * 2;
                float bl0 = g_blab[bb * 128 + c];
                float bl1 = g_blab[bb * 128 + c + 1];
                if (trow < TT) {
                    float2 v = make_float2(d[mi][nj][0] + bl0, d[mi][nj][1] + bl1);
                    *(float2*)&g_lab[(size_t)(bb * TT + trow) * 128 + c] = v;
                }
                if (trow + 8 < TT) {
                    float2 v = make_float2(d[mi][nj][2] + bl0, d[mi][nj][3] + bl1);
                    *(float2*)&g_lab[(size_t)(bb * TT + trow + 8) * 128 + c] = v;
                }
            }
        }
    }
}

// ---------------- kernel 3: fixup — g_lab <- g_lab/ln2 - log2(sumexp)  (log2-domain log-probs)
__global__ __launch_bounds__(256)
void fixup_kernel() {
    int idx = blockIdx.x * blockDim.x + threadIdx.x;
    if (idx >= MROWS * 26) return;
    int row = idx / 26;
    int q = idx - row * 26;
    float ls = lg2f(__ldg(&g_sumexp[row]));
    float4* p = ((float4*)g_lab) + (size_t)row * 32 + q;
    float4 v = *p;
    v.x = v.x * INVLN2 - ls;
    v.y = v.y * INVLN2 - ls;
    v.z = v.z * INVLN2 - ls;
    v.w = v.w * INVLN2 - ls;
    *p = v;
}

// ---------------- kernel 4: CTC forward DP — warp-skewed wavefront, no barriers ----------------
__global__ __launch_bounds__(224)
void ctc_dp_kernel(const int* __restrict__ ys, const int* __restrict__ elens,
                   const int* __restrict__ ylens, float* __restrict__ out) {
    const int b    = blockIdx.x;
    const int tid  = threadIdx.x;
    const int lane = tid & 31;
    const int w    = tid >> 5;          // 0..6
    const int s    = tid;               // state index

    __shared__ uint4 bnd[7][RING];      // {tag, a[32w+30], a[32w+31], tag}
    __shared__ volatile int prog[8];
    __shared__ float afin[224];

    const int ylen = ylens[b];
    const int tend = elens[b] - 1;

    const bool in_s  = (s < SS);
    const bool valid = in_s && (s <= 2 * ylen);
    const int  li    = (s & 1) ? (s >> 1) + 1 : 0;   // <= 112, in-row for all tid<224
    bool skip = false;
    if (in_s && (s & 1) && s >= 3)
        skip = (ys[b * LL + (s >> 1)] != ys[b * LL + (s >> 1) - 1]);

    const float* lpbase = g_lab + (size_t)b * TT * 128 + li;

    if (tid < 8) prog[tid] = 0;

    // t = 0 init (g_lab already holds log2-softmax)
    float a = NEG_INF;
    if (s < 2) {
        a = lpbase[0];
        if (!valid) a = NEG_INF;
    }

    const unsigned bnd_self = smem_u32(&bnd[w][0]);
    const unsigned bnd_prev = smem_u32(&bnd[(w > 0 ? w - 1 : 0)][0]);

    {   // publish t=0 boundary
        float v30 = __shfl_sync(0xffffffffu, a, 30);
        if (w < 6 && lane == 31) st_bnd(bnd_self, 0u, v30, a);
    }
    __syncthreads();   // boundaries + prog init visible to all warps

    // lp prefetch FIFO (depth 4; pad rows in g_lab cover the overrun)
    float f0 = __ldg(lpbase + 1 * 128);
    float f1 = __ldg(lpbase + 2 * 128);
    float f2 = __ldg(lpbase + 3 * 128);
    float f3 = __ldg(lpbase + 4 * 128);

    for (int t = 1; t <= tend; ++t) {
        float a2 = __shfl_up_sync(0xffffffffu, a, 1);
        float a3 = __shfl_up_sync(0xffffffffu, a, 2);
        if (w > 0) {
            unsigned addr = bnd_prev + ((unsigned)(t - 1) & (RING - 1)) * 16u;
            unsigned tagu = (unsigned)(t - 1);
            uint4 bv;
            do { bv = ld_bnd(addr); } while (bv.x != tagu || bv.w != tagu);
            if (lane == 0)      { a2 = __uint_as_float(bv.z); a3 = __uint_as_float(bv.y); }
            else if (lane == 1) { a3 = __uint_as_float(bv.z); }
        } else {
            if (lane == 0)      { a2 = NEG_INF; a3 = NEG_INF; }
            else if (lane == 1) { a3 = NEG_INF; }
        }
        if (!skip) a3 = NEG_INF;

        float lp = f0; f0 = f1; f1 = f2; f2 = f3;
        f3 = __ldg(lpbase + (size_t)(t + 4) * 128);

        float m  = fmaxf(a, fmaxf(a2, a3));
        float su = ex2f(a - m) + ex2f(a2 - m) + ex2f(a3 - m);
        float nv = m + lg2f(su) + lp;
        a = valid ? nv : NEG_INF;

        float v30 = __shfl_sync(0xffffffffu, a, 30);
        if (w < 6) {
            if (t >= RING) { while (prog[w + 1] < t - RING + 1) { } }   // back-pressure (rare)
            if (lane == 31) st_bnd(bnd_self + ((unsigned)t & (RING - 1)) * 16u, (unsigned)t, v30, a);
        }
        if (lane == 31) prog[w] = t;
    }

    afin[tid] = a;
    __syncthreads();

    if (tid == 0) {
        float last = afin[2 * ylen];
        float prev = afin[2 * ylen - 1];
        float mm = fmaxf(last, prev);
        float l2v = mm + lg2f(ex2f(last - mm) + ex2f(prev - mm));
        float lnat = -l2v * LN2;
        if (!(lnat < -0.5f * NEG_INF)) lnat = 0.0f;   // zero_infinity
        atomicAdd(out, lnat * (1.0f / (float)BB));
    }
}

// ---------------- launch ----------------
extern "C" void kernel_launch(void* const* d_in, const int* in_sizes, int n_in,
                              void* d_out, int out_size) {
    const float* eouts = (const float*)d_in[0];
    const float* W     = (const float*)d_in[1];
    const float* bias  = (const float*)d_in[2];
    const int*   ys    = (const int*)d_in[3];
    const int*   elens = (const int*)d_in[4];
    const int*   ylens = (const int*)d_in[5];
    float* out = (float*)d_out;

    prep_kernel<<<2048, 256>>>(eouts, W, bias, ys, out, out_size);
    gemm_fused_kernel<<<4256, 256>>>(bias);
    fixup_kernel<<<(MROWS * 26 + 255) / 256, 256>>>();
    ctc_dp_kernel<<<BB, 224>>>(ys, elens, ylens, out);
}

// round 5
// speedup vs baseline: 1.6511x; 1.6511x over previous
#include <cuda_runtime.h>
#include <cuda_bf16.h>

#define NEG_INF (-1e10f)
#define INVLN2 1.4426950408889634f
#define LN2    0.6931471805599453f

// Problem constants
#define BB 32
#define TT 1000
#define HH 512
#define VV 2048
#define LL 100
#define SS 201
#define MROWS (BB*TT)          // 32000
#define MPAD  (MROWS + 64)     // padding for DP prefetch overrun

// ---------------- static device scratch (no allocation allowed) ----------------
__device__ __align__(16) static __nv_bfloat16 g_X[MROWS * HH];        // eouts bf16
__device__ __align__(16) static __nv_bfloat16 g_W[VV * HH];           // W bf16
__device__ __align__(16) static __nv_bfloat16 g_Wlab[BB * 128 * HH];  // gathered label weights
__device__ __align__(16) static float         g_blab[BB * 128];       // gathered label bias
__device__ __align__(16) static float         g_sumexp[MPAD];         // per-row sum(exp(logit))
__device__ __align__(16) static float         g_lab[(size_t)MPAD * 128]; // logits -> log2 softmax

// ---------------- helpers ----------------
__device__ __forceinline__ unsigned smem_u32(const void* p) {
    return (unsigned)__cvta_generic_to_shared(p);
}

#define CP_ASYNC16(dst, src) \
    asm volatile("cp.async.ca.shared.global [%0], [%1], 16;\n" :: "r"(dst), "l"(src) : "memory")
#define CP_COMMIT() asm volatile("cp.async.commit_group;\n" ::: "memory")
#define CP_WAIT1()  asm volatile("cp.async.wait_group 1;\n" ::: "memory")

__device__ __forceinline__ void ldmatrix_x4(unsigned* r, unsigned addr) {
    asm volatile("ldmatrix.sync.aligned.m8n8.x4.shared.b16 {%0,%1,%2,%3}, [%4];\n"
                 : "=r"(r[0]), "=r"(r[1]), "=r"(r[2]), "=r"(r[3]) : "r"(addr));
}

__device__ __forceinline__ void mma_bf16(float* d, const unsigned* a, unsigned b0, unsigned b1) {
    asm volatile("mma.sync.aligned.m16n8k16.row.col.f32.bf16.bf16.f32 "
                 "{%0,%1,%2,%3}, {%4,%5,%6,%7}, {%8,%9}, {%0,%1,%2,%3};\n"
                 : "+f"(d[0]), "+f"(d[1]), "+f"(d[2]), "+f"(d[3])
                 : "r"(a[0]), "r"(a[1]), "r"(a[2]), "r"(a[3]), "r"(b0), "r"(b1));
}

__device__ __forceinline__ float ex2f(float x) {
    float y; asm("ex2.approx.f32 %0, %1;" : "=f"(y) : "f"(x)); return y;
}
__device__ __forceinline__ float lg2f(float x) {
    float y; asm("lg2.approx.f32 %0, %1;" : "=f"(y) : "f"(x)); return y;
}

// ---------------- kernel 1: convert + gather + zero scratch/out ----------------
__global__ void prep_kernel(const float* __restrict__ eouts, const float* __restrict__ W,
                            const float* __restrict__ bias, const int* __restrict__ ys,
                            float* __restrict__ out, int out_size) {
    int i = blockIdx.x * blockDim.x + threadIdx.x;
    int stride = gridDim.x * blockDim.x;
    for (int k = i; k < MROWS * HH; k += stride) g_X[k] = __float2bfloat16(eouts[k]);
    for (int k = i; k < VV * HH; k += stride)    g_W[k] = __float2bfloat16(W[k]);
    for (int k = i; k < BB * 128 * HH; k += stride) {
        int kk = k & (HH - 1);
        int j  = (k >> 9) & 127;
        int b  = k >> 16;
        int v  = (j == 0) ? 0 : ((j <= LL) ? ys[b * LL + (j - 1)] : -1);
        g_Wlab[k] = (v >= 0) ? __float2bfloat16(W[(size_t)v * HH + kk]) : __float2bfloat16(0.0f);
    }
    for (int k = i; k < BB * 128; k += stride) {
        int j = k & 127;
        int b = k >> 7;
        int v = (j == 0) ? 0 : ((j <= LL) ? ys[b * LL + (j - 1)] : -1);
        g_blab[k] = (v >= 0) ? bias[v] : 0.0f;
    }
    for (int k = i; k < MPAD; k += stride) g_sumexp[k] = 0.0f;
    for (int k = i; k < out_size; k += stride) out[k] = 0.0f;
}

// ---------------- kernel 2: fused bf16 tensor-core GEMMs ----------------
// blocks [0, 4000):  full-V GEMM, epilogue reduces sum(exp(logit+bias)) -> atomicAdd g_sumexp
// blocks [4000, 4256): label GEMM per batch, epilogue stores logit+bias to g_lab
__global__ __launch_bounds__(256)
void gemm_fused_kernel(const float* __restrict__ bias) {
    __shared__ __nv_bfloat16 As[2][128 * 24];
    __shared__ __nv_bfloat16 Bs[2][128 * 24];

    const int flat = blockIdx.x;
    const bool mode0 = (flat < 4000);
    const int bx = mode0 ? (flat % 250) : ((flat - 4000) & 7);
    const int by = mode0 ? (flat / 250) : ((flat - 4000) >> 3);

    const int tid = threadIdx.x, lane = tid & 31, wid = tid >> 5;
    const int wm = (wid & 3) * 32;
    const int wn = (wid >> 2) * 64;

    const int ldrow = tid >> 1;
    const int ldcol = (tid & 1) * 8;

    const __nv_bfloat16* Ag;
    const __nv_bfloat16* Bg;
    int bb = 0;
    if (mode0) {
        Ag = g_X + (size_t)(bx * 128 + ldrow) * HH + ldcol;
        Bg = g_W + (size_t)(by * 128 + ldrow) * HH + ldcol;
    } else {
        bb = by;
        int t = bx * 128 + ldrow;
        if (t > TT - 1) t = TT - 1;  // clamp (values unused)
        Ag = g_X    + (size_t)(bb * TT + t) * HH + ldcol;
        Bg = g_Wlab + (size_t)(bb * 128 + ldrow) * HH + ldcol;
    }
    const int soff = ldrow * 24 + ldcol;

    float d[2][8][4];
#pragma unroll
    for (int mi = 0; mi < 2; mi++)
#pragma unroll
        for (int nj = 0; nj < 8; nj++)
#pragma unroll
            for (int q = 0; q < 4; q++) d[mi][nj][q] = 0.0f;

    unsigned aAddr[2], bAddr[4];
#pragma unroll
    for (int mi = 0; mi < 2; mi++)
        aAddr[mi] = smem_u32(&As[0][(wm + mi * 16 + (lane & 15)) * 24 + (lane >> 4) * 8]);
#pragma unroll
    for (int np = 0; np < 4; np++) {
        int r = wn + np * 16 + (lane & 7) + ((lane >> 4) & 1) * 8;
        int c = ((lane >> 3) & 1) * 8;
        bAddr[np] = smem_u32(&Bs[0][r * 24 + c]);
    }

    {
        CP_ASYNC16(smem_u32(&As[0][soff]), Ag + 0);
        CP_ASYNC16(smem_u32(&Bs[0][soff]), Bg + 0);
        CP_COMMIT();
        CP_ASYNC16(smem_u32(&As[1][soff]), Ag + 16);
        CP_ASYNC16(smem_u32(&Bs[1][soff]), Bg + 16);
        CP_COMMIT();
    }

    for (int kt = 0; kt < HH / 16; kt++) {
        CP_WAIT1();
        __syncthreads();
        const int buf = kt & 1;
        const unsigned off = buf * 6144u;

        unsigned ra[2][4], rb[4][4];
#pragma unroll
        for (int mi = 0; mi < 2; mi++) ldmatrix_x4(ra[mi], aAddr[mi] + off);
#pragma unroll
        for (int np = 0; np < 4; np++) ldmatrix_x4(rb[np], bAddr[np] + off);
        __syncthreads();

        if (kt + 2 < HH / 16) {
            int k0 = (kt + 2) * 16;
            CP_ASYNC16(smem_u32(&As[buf][soff]), Ag + k0);
            CP_ASYNC16(smem_u32(&Bs[buf][soff]), Bg + k0);
            CP_COMMIT();
        } else {
            CP_COMMIT();
        }

#pragma unroll
        for (int mi = 0; mi < 2; mi++)
#pragma unroll
            for (int nj = 0; nj < 8; nj++) {
                int np = nj >> 1;
                unsigned b0 = (nj & 1) ? rb[np][2] : rb[np][0];
                unsigned b1 = (nj & 1) ? rb[np][3] : rb[np][1];
                mma_bf16(d[mi][nj], ra[mi], b0, b1);
            }
    }

    // ---------------- epilogue ----------------
    if (mode0) {
#pragma unroll
        for (int mi = 0; mi < 2; mi++) {
            float se0 = 0.0f, se1 = 0.0f;
            int r = bx * 128 + wm + mi * 16 + (lane >> 2);
#pragma unroll
            for (int nj = 0; nj < 8; nj++) {
                int c = by * 128 + wn + nj * 8 + (lane & 3) * 2;
                float b0 = __ldg(&bias[c]);
                float b1 = __ldg(&bias[c + 1]);
                se0 += __expf(d[mi][nj][0] + b0) + __expf(d[mi][nj][1] + b1);
                se1 += __expf(d[mi][nj][2] + b0) + __expf(d[mi][nj][3] + b1);
            }
            se0 += __shfl_xor_sync(0xffffffffu, se0, 1);
            se0 += __shfl_xor_sync(0xffffffffu, se0, 2);
            se1 += __shfl_xor_sync(0xffffffffu, se1, 1);
            se1 += __shfl_xor_sync(0xffffffffu, se1, 2);
            if ((lane & 3) == 0) {
                atomicAdd(&g_sumexp[r], se0);
                atomicAdd(&g_sumexp[r + 8], se1);
            }
        }
    } else {
#pragma unroll
        for (int mi = 0; mi < 2; mi++) {
            int trow = bx * 128 + wm + mi * 16 + (lane >> 2);
#pragma unroll
            for (int nj = 0; nj < 8; nj++) {
                int c = wn + nj * 8 + (lane & 3) * 2;
                float bl0 = g_blab[bb * 128 + c];
                float bl1 = g_blab[bb * 128 + c + 1];
                if (trow < TT) {
                    float2 v = make_float2(d[mi][nj][0] + bl0, d[mi][nj][1] + bl1);
                    *(float2*)&g_lab[(size_t)(bb * TT + trow) * 128 + c] = v;
                }
                if (trow + 8 < TT) {
                    float2 v = make_float2(d[mi][nj][2] + bl0, d[mi][nj][3] + bl1);
                    *(float2*)&g_lab[(size_t)(bb * TT + trow + 8) * 128 + c] = v;
                }
            }
        }
    }
}

// ---------------- kernel 3: fixup — g_lab <- g_lab/ln2 - log2(sumexp)  (log2-domain log-probs)
__global__ __launch_bounds__(256)
void fixup_kernel() {
    int idx = blockIdx.x * blockDim.x + threadIdx.x;
    if (idx >= MROWS * 26) return;
    int row = idx / 26;
    int q = idx - row * 26;
    float ls = lg2f(__ldg(&g_sumexp[row]));
    float4* p = ((float4*)g_lab) + (size_t)row * 32 + q;
    float4 v = *p;
    v.x = v.x * INVLN2 - ls;
    v.y = v.y * INVLN2 - ls;
    v.z = v.z * INVLN2 - ls;
    v.w = v.w * INVLN2 - ls;
    *p = v;
}

// ---------------- kernel 4: CTC forward DP — log2 domain, register trapezoid ----------------
// 8 warps; warp w holds 32 states s = 26w - 6 + lane in registers (6-state left halo).
// 3 DP steps via shfl_up only (validity shrinks 2 lanes/step; lanes >= 6 exact),
// then one STS + __syncthreads + LDS exchange through a ping-ponged alpha array.
__global__ __launch_bounds__(256)
void ctc_dp_kernel(const int* __restrict__ ys, const int* __restrict__ elens,
                   const int* __restrict__ ylens, float* __restrict__ out) {
    const int b    = blockIdx.x;
    const int tid  = threadIdx.x;
    const int lane = tid & 31;
    const int w    = tid >> 5;              // 0..7
    const int s    = w * 26 + lane - 6;     // state (may be <0 or >200 = halo/garbage)

    __shared__ float Asd[2][202];
    __shared__ float qbuf[2][24][128];      // 24 staged frames of lp2, double buffered

    const int ylen = ylens[b];
    const int tend = elens[b] - 1;

    const bool in_s  = (s >= 0 && s <= 200);
    const bool valid = in_s && (s <= 2 * ylen);
    const int  sc    = (s < 0) ? 0 : ((s > 200) ? 200 : s);
    const int  li    = (sc & 1) ? ((sc >> 1) + 1) : 0;      // <= 100 < 104 fixed columns
    bool skipf = false;
    if (valid && (s & 1) && s >= 3)
        skipf = (ys[b * LL + (s >> 1)] != ys[b * LL + (s >> 1) - 1]);

    // t = 0 init: every lane computes its state's alpha_0 (halo copies consistent)
    float a = NEG_INF;
    if (valid && s < 2) a = g_lab[(size_t)(b * TT) * 128 + li];

    // stage chunk cc = frames [1 + 24*cc, 1 + 24*cc + 24)
    auto stage = [&](int cc, int bf) {
        int t0 = 1 + cc * 24;
        const float4* src = (const float4*)(g_lab + (size_t)(b * TT + t0) * 128);
        unsigned dst = smem_u32(&qbuf[bf][0][0]);
#pragma unroll
        for (int i = 0; i < 3; i++) {
            int idx = tid + 256 * i;        // 768 float4 per chunk
            CP_ASYNC16(dst + (unsigned)idx * 16u, src + idx);
        }
        CP_COMMIT();
    };

    stage(0, 0);
    stage(1, 1);

    int wb = 0, lastwb = 0;
    int t = 1, c = 0;
    while (t <= tend) {
        CP_WAIT1();
        __syncthreads();                    // chunk staged for everyone
        const int bf = c & 1;
        const int nfr = min(24, tend - t + 1);
        int fr = 0;
        while (fr < nfr) {
            const int jn = min(3, nfr - fr);
#pragma unroll 3
            for (int j = 0; j < jn; j++) {
                float a2 = __shfl_up_sync(0xffffffffu, a, 1);
                float a3 = __shfl_up_sync(0xffffffffu, a, 2);
                if (!skipf) a3 = NEG_INF;
                float lp = qbuf[bf][fr + j][li];
                float m  = fmaxf(a, fmaxf(a2, a3));
                float su = ex2f(a - m) + ex2f(a2 - m) + ex2f(a3 - m);
                float nv = m + lg2f(su) + lp;
                a = valid ? nv : NEG_INF;
            }
            if (lane >= 2 * jn && in_s) Asd[wb][s] = a;   // overlapping commits are bit-identical
            __syncthreads();
            a = in_s ? Asd[wb][s] : NEG_INF;
            lastwb = wb; wb ^= 1;
            fr += jn;
        }
        if (nfr == 24) stage(c + 2, bf);    // refill consumed buffer (pad rows cover overrun)
        t += nfr; c++;
    }

    if (tid == 0) {
        float last = Asd[lastwb][2 * ylen];
        float prev = Asd[lastwb][2 * ylen - 1];
        float mm = fmaxf(last, prev);
        float l2v = mm + lg2f(ex2f(last - mm) + ex2f(prev - mm));
        float lnat = -l2v * LN2;
        if (!(lnat < -0.5f * NEG_INF)) lnat = 0.0f;   // zero_infinity
        atomicAdd(out, lnat * (1.0f / (float)BB));
    }
}

// ---------------- launch ----------------
extern "C" void kernel_launch(void* const* d_in, const int* in_sizes, int n_in,
                              void* d_out, int out_size) {
    const float* eouts = (const float*)d_in[0];
    const float* W     = (const float*)d_in[1];
    const float* bias  = (const float*)d_in[2];
    const int*   ys    = (const int*)d_in[3];
    const int*   elens = (const int*)d_in[4];
    const int*   ylens = (const int*)d_in[5];
    float* out = (float*)d_out;

    prep_kernel<<<2048, 256>>>(eouts, W, bias, ys, out, out_size);
    gemm_fused_kernel<<<4256, 256>>>(bias);
    fixup_kernel<<<(MROWS * 26 + 255) / 256, 256>>>();
    ctc_dp_kernel<<<BB, 256>>>(ys, elens, ylens, out);
}

// round 7
// speedup vs baseline: 1.7681x; 1.0708x over previous
#include <cuda_runtime.h>
#include <cuda_bf16.h>
#include <cstdint>

#define NEG_INF (-1e10f)
#define INVLN2 1.4426950408889634f
#define LN2    0.6931471805599453f

// Problem constants
#define BB 32
#define TT 1000
#define HH 512
#define VV 2048
#define LL 100
#define SS 201
#define MROWS (BB*TT)          // 32000
#define MPAD  (MROWS + 64)     // padding for DP prefetch overrun

// fp8 scaling: X*4, W*16 -> logits scaled by 64; descale in epilogue
#define XSCALE 4.0f
#define WSCALE 16.0f
#define DESCALE (1.0f / 64.0f)

// ---------------- static device scratch (no allocation allowed) ----------------
__device__ __align__(16) static __nv_bfloat16 g_X[MROWS * HH];          // eouts bf16 (label gemm)
__device__ __align__(16) static unsigned short g_X8[MROWS * HH / 2];    // eouts e4m3 pairs (*4)
__device__ __align__(16) static unsigned short g_W8[VV * HH / 2];       // W e4m3 pairs (*16)
__device__ __align__(16) static __nv_bfloat16 g_Wlab[BB * 128 * HH];    // gathered label weights
__device__ __align__(16) static float         g_blab[BB * 128];         // gathered label bias
__device__ __align__(16) static float         g_sumexp[MPAD];           // per-row sum(exp(logit))
__device__ __align__(16) static float         g_lab[(size_t)MPAD * 128];// logits -> log2 softmax

// ---------------- helpers ----------------
__device__ __forceinline__ unsigned smem_u32(const void* p) {
    return (unsigned)__cvta_generic_to_shared(p);
}

#define CP_ASYNC16(dst, src) \
    asm volatile("cp.async.ca.shared.global [%0], [%1], 16;\n" :: "r"(dst), "l"(src) : "memory")
#define CP_COMMIT() asm volatile("cp.async.commit_group;\n" ::: "memory")
#define CP_WAIT1()  asm volatile("cp.async.wait_group 1;\n" ::: "memory")

__device__ __forceinline__ void ldmatrix_x4(unsigned* r, unsigned addr) {
    asm volatile("ldmatrix.sync.aligned.m8n8.x4.shared.b16 {%0,%1,%2,%3}, [%4];\n"
                 : "=r"(r[0]), "=r"(r[1]), "=r"(r[2]), "=r"(r[3]) : "r"(addr));
}

__device__ __forceinline__ void mma_bf16(float* d, const unsigned* a, unsigned b0, unsigned b1) {
    asm volatile("mma.sync.aligned.m16n8k16.row.col.f32.bf16.bf16.f32 "
                 "{%0,%1,%2,%3}, {%4,%5,%6,%7}, {%8,%9}, {%0,%1,%2,%3};\n"
                 : "+f"(d[0]), "+f"(d[1]), "+f"(d[2]), "+f"(d[3])
                 : "r"(a[0]), "r"(a[1]), "r"(a[2]), "r"(a[3]), "r"(b0), "r"(b1));
}

__device__ __forceinline__ void mma_fp8(float* d, const unsigned* a, unsigned b0, unsigned b1) {
    asm volatile("mma.sync.aligned.m16n8k32.row.col.f32.e4m3.e4m3.f32 "
                 "{%0,%1,%2,%3}, {%4,%5,%6,%7}, {%8,%9}, {%0,%1,%2,%3};\n"
                 : "+f"(d[0]), "+f"(d[1]), "+f"(d[2]), "+f"(d[3])
                 : "r"(a[0]), "r"(a[1]), "r"(a[2]), "r"(a[3]), "r"(b0), "r"(b1));
}

__device__ __forceinline__ float ex2f(float x) {
    float y; asm("ex2.approx.f32 %0, %1;" : "=f"(y) : "f"(x)); return y;
}
__device__ __forceinline__ float lg2f(float x) {
    float y; asm("lg2.approx.f32 %0, %1;" : "=f"(y) : "f"(x)); return y;
}

// pack two floats into e4m3x2 (lo = first elem, hi = second elem)
__device__ __forceinline__ unsigned short fp8pack(float lo, float hi) {
    unsigned short h;
    asm("cvt.rn.satfinite.e4m3x2.f32 %0, %1, %2;" : "=h"(h) : "f"(hi), "f"(lo));
    return h;
}

// ---------------- kernel 1: convert + gather + zero scratch/out ----------------
__global__ void prep_kernel(const float* __restrict__ eouts, const float* __restrict__ W,
                            const float* __restrict__ bias, const int* __restrict__ ys,
                            float* __restrict__ out, int out_size) {
    int i = blockIdx.x * blockDim.x + threadIdx.x;
    int stride = gridDim.x * blockDim.x;
    // bf16 X (for label gemm) + fp8 X (for full-V gemm)
    for (int k = i; k < MROWS * HH / 2; k += stride) {
        float2 v = ((const float2*)eouts)[k];
        g_X[2 * k]     = __float2bfloat16(v.x);
        g_X[2 * k + 1] = __float2bfloat16(v.y);
        g_X8[k] = fp8pack(v.x * XSCALE, v.y * XSCALE);
    }
    for (int k = i; k < VV * HH / 2; k += stride) {
        float2 v = ((const float2*)W)[k];
        g_W8[k] = fp8pack(v.x * WSCALE, v.y * WSCALE);
    }
    for (int k = i; k < BB * 128 * HH; k += stride) {
        int kk = k & (HH - 1);
        int j  = (k >> 9) & 127;
        int b  = k >> 16;
        int v  = (j == 0) ? 0 : ((j <= LL) ? ys[b * LL + (j - 1)] : -1);
        g_Wlab[k] = (v >= 0) ? __float2bfloat16(W[(size_t)v * HH + kk]) : __float2bfloat16(0.0f);
    }
    for (int k = i; k < BB * 128; k += stride) {
        int j = k & 127;
        int b = k >> 7;
        int v = (j == 0) ? 0 : ((j <= LL) ? ys[b * LL + (j - 1)] : -1);
        g_blab[k] = (v >= 0) ? bias[v] : 0.0f;
    }
    for (int k = i; k < MPAD; k += stride) g_sumexp[k] = 0.0f;
    for (int k = i; k < out_size; k += stride) out[k] = 0.0f;
}

// ---------------- kernel 2: fp8 tensor-core full-V GEMM + sumexp epilogue ----------------
// grid (250, 16): 128x128 logits tile, K=512 fp8 (16 k-tiles of 32).
// SMEM tiles stored as u16 = fp8 pairs: row = 16 u16 data + 8 u16 pad (identical
// ldmatrix/fragment layout to the proven bf16 16816 kernel, scaled 2x in K).
__global__ __launch_bounds__(256)
void gemm8_kernel(const float* __restrict__ bias) {
    __shared__ unsigned short As[2][128 * 24];
    __shared__ unsigned short Bs[2][128 * 24];

    const int bx = blockIdx.x, by = blockIdx.y;
    const int tid = threadIdx.x, lane = tid & 31, wid = tid >> 5;
    const int wm = (wid & 3) * 32;
    const int wn = (wid >> 2) * 64;

    const int ldrow = tid >> 1;         // 0..127
    const int ldcol = (tid & 1) * 8;    // 0 or 8 (u16 units)

    // u16-granular global pointers: 256 u16 per row
    const unsigned short* Ag = g_X8 + (size_t)(bx * 128 + ldrow) * 256 + ldcol;
    const unsigned short* Bg = g_W8 + (size_t)(by * 128 + ldrow) * 256 + ldcol;
    const int soff = ldrow * 24 + ldcol;

    float d[2][8][4];
#pragma unroll
    for (int mi = 0; mi < 2; mi++)
#pragma unroll
        for (int nj = 0; nj < 8; nj++)
#pragma unroll
            for (int q = 0; q < 4; q++) d[mi][nj][q] = 0.0f;

    unsigned aAddr[2], bAddr[4];
#pragma unroll
    for (int mi = 0; mi < 2; mi++)
        aAddr[mi] = smem_u32(&As[0][(wm + mi * 16 + (lane & 15)) * 24 + (lane >> 4) * 8]);
#pragma unroll
    for (int np = 0; np < 4; np++) {
        int r = wn + np * 16 + (lane & 7) + ((lane >> 4) & 1) * 8;
        int c = ((lane >> 3) & 1) * 8;
        bAddr[np] = smem_u32(&Bs[0][r * 24 + c]);
    }

    {
        CP_ASYNC16(smem_u32(&As[0][soff]), Ag + 0);
        CP_ASYNC16(smem_u32(&Bs[0][soff]), Bg + 0);
        CP_COMMIT();
        CP_ASYNC16(smem_u32(&As[1][soff]), Ag + 16);
        CP_ASYNC16(smem_u32(&Bs[1][soff]), Bg + 16);
        CP_COMMIT();
    }

    // 16 k-tiles of 32 fp8 (= 16 u16 columns each)
    for (int kt = 0; kt < 16; kt++) {
        CP_WAIT1();
        __syncthreads();
        const int buf = kt & 1;
        const unsigned off = buf * 6144u;   // 128*24*2 bytes

        unsigned ra[2][4], rb[4][4];
#pragma unroll
        for (int mi = 0; mi < 2; mi++) ldmatrix_x4(ra[mi], aAddr[mi] + off);
#pragma unroll
        for (int np = 0; np < 4; np++) ldmatrix_x4(rb[np], bAddr[np] + off);
        __syncthreads();

        if (kt + 2 < 16) {
            int k0 = (kt + 2) * 16;
            CP_ASYNC16(smem_u32(&As[buf][soff]), Ag + k0);
            CP_ASYNC16(smem_u32(&Bs[buf][soff]), Bg + k0);
            CP_COMMIT();
        } else {
            CP_COMMIT();
        }

#pragma unroll
        for (int mi = 0; mi < 2; mi++)
#pragma unroll
            for (int nj = 0; nj < 8; nj++) {
                int np = nj >> 1;
                unsigned b0 = (nj & 1) ? rb[np][2] : rb[np][0];
                unsigned b1 = (nj & 1) ? rb[np][3] : rb[np][1];
                mma_fp8(d[mi][nj], ra[mi], b0, b1);
            }
    }

    // epilogue: row sums of exp(logit) in log2 domain; descale fp8 product by 1/64
    const float dsc = INVLN2 * DESCALE;
#pragma unroll
    for (int mi = 0; mi < 2; mi++) {
        float se0 = 0.0f, se1 = 0.0f;
        int r = bx * 128 + wm + mi * 16 + (lane >> 2);
#pragma unroll
        for (int nj = 0; nj < 8; nj++) {
            int c = by * 128 + wn + nj * 8 + (lane & 3) * 2;
            float b0 = __ldg(&bias[c]) * INVLN2;
            float b1 = __ldg(&bias[c + 1]) * INVLN2;
            se0 += ex2f(fmaf(d[mi][nj][0], dsc, b0)) + ex2f(fmaf(d[mi][nj][1], dsc, b1));
            se1 += ex2f(fmaf(d[mi][nj][2], dsc, b0)) + ex2f(fmaf(d[mi][nj][3], dsc, b1));
        }
        se0 += __shfl_xor_sync(0xffffffffu, se0, 1);
        se0 += __shfl_xor_sync(0xffffffffu, se0, 2);
        se1 += __shfl_xor_sync(0xffffffffu, se1, 1);
        se1 += __shfl_xor_sync(0xffffffffu, se1, 2);
        if ((lane & 3) == 0) {
            atomicAdd(&g_sumexp[r], se0);
            atomicAdd(&g_sumexp[r + 8], se1);
        }
    }
}

// ---------------- kernel 3: label GEMM (bf16 mma.sync) ----------------
// grid 256: bx = blockIdx & 7 (M-tile of 128 frames), bb = blockIdx >> 3 (batch)
__global__ __launch_bounds__(256)
void gemm_label_kernel() {
    __shared__ __nv_bfloat16 As[2][128 * 24];
    __shared__ __nv_bfloat16 Bs[2][128 * 24];

    const int bx = blockIdx.x & 7;
    const int bb = blockIdx.x >> 3;

    const int tid = threadIdx.x, lane = tid & 31, wid = tid >> 5;
    const int wm = (wid & 3) * 32;
    const int wn = (wid >> 2) * 64;

    const int ldrow = tid >> 1;
    const int ldcol = (tid & 1) * 8;

    int t = bx * 128 + ldrow;
    if (t > TT - 1) t = TT - 1;  // clamp (values unused)
    const __nv_bfloat16* Ag = g_X    + (size_t)(bb * TT + t) * HH + ldcol;
    const __nv_bfloat16* Bg = g_Wlab + (size_t)(bb * 128 + ldrow) * HH + ldcol;
    const int soff = ldrow * 24 + ldcol;

    float d[2][8][4];
#pragma unroll
    for (int mi = 0; mi < 2; mi++)
#pragma unroll
        for (int nj = 0; nj < 8; nj++)
#pragma unroll
            for (int q = 0; q < 4; q++) d[mi][nj][q] = 0.0f;

    unsigned aAddr[2], bAddr[4];
#pragma unroll
    for (int mi = 0; mi < 2; mi++)
        aAddr[mi] = smem_u32(&As[0][(wm + mi * 16 + (lane & 15)) * 24 + (lane >> 4) * 8]);
#pragma unroll
    for (int np = 0; np < 4; np++) {
        int r = wn + np * 16 + (lane & 7) + ((lane >> 4) & 1) * 8;
        int c = ((lane >> 3) & 1) * 8;
        bAddr[np] = smem_u32(&Bs[0][r * 24 + c]);
    }

    {
        CP_ASYNC16(smem_u32(&As[0][soff]), Ag + 0);
        CP_ASYNC16(smem_u32(&Bs[0][soff]), Bg + 0);
        CP_COMMIT();
        CP_ASYNC16(smem_u32(&As[1][soff]), Ag + 16);
        CP_ASYNC16(smem_u32(&Bs[1][soff]), Bg + 16);
        CP_COMMIT();
    }

    for (int kt = 0; kt < HH / 16; kt++) {
        CP_WAIT1();
        __syncthreads();
        const int buf = kt & 1;
        const unsigned off = buf * 6144u;

        unsigned ra[2][4], rb[4][4];
#pragma unroll
        for (int mi = 0; mi < 2; mi++) ldmatrix_x4(ra[mi], aAddr[mi] + off);
#pragma unroll
        for (int np = 0; np < 4; np++) ldmatrix_x4(rb[np], bAddr[np] + off);
        __syncthreads();

        if (kt + 2 < HH / 16) {
            int k0 = (kt + 2) * 16;
            CP_ASYNC16(smem_u32(&As[buf][soff]), Ag + k0);
            CP_ASYNC16(smem_u32(&Bs[buf][soff]), Bg + k0);
            CP_COMMIT();
        } else {
            CP_COMMIT();
        }

#pragma unroll
        for (int mi = 0; mi < 2; mi++)
#pragma unroll
            for (int nj = 0; nj < 8; nj++) {
                int np = nj >> 1;
                unsigned b0 = (nj & 1) ? rb[np][2] : rb[np][0];
                unsigned b1 = (nj & 1) ? rb[np][3] : rb[np][1];
                mma_bf16(d[mi][nj], ra[mi], b0, b1);
            }
    }

#pragma unroll
    for (int mi = 0; mi < 2; mi++) {
        int trow = bx * 128 + wm + mi * 16 + (lane >> 2);
#pragma unroll
        for (int nj = 0; nj < 8; nj++) {
            int c = wn + nj * 8 + (lane & 3) * 2;
            float bl0 = g_blab[bb * 128 + c];
            float bl1 = g_blab[bb * 128 + c + 1];
            if (trow < TT) {
                float2 v = make_float2(d[mi][nj][0] + bl0, d[mi][nj][1] + bl1);
                *(float2*)&g_lab[(size_t)(bb * TT + trow) * 128 + c] = v;
            }
            if (trow + 8 < TT) {
                float2 v = make_float2(d[mi][nj][2] + bl0, d[mi][nj][3] + bl1);
                *(float2*)&g_lab[(size_t)(bb * TT + trow + 8) * 128 + c] = v;
            }
        }
    }
}

// ---------------- kernel 4: fixup — g_lab <- g_lab/ln2 - log2(sumexp) ----------------
__global__ __launch_bounds__(256)
void fixup_kernel() {
    int idx = blockIdx.x * blockDim.x + threadIdx.x;
    if (idx >= MROWS * 26) return;
    int row = idx / 26;
    int q = idx - row * 26;
    float ls = lg2f(__ldg(&g_sumexp[row]));
    float4* p = ((float4*)g_lab) + (size_t)row * 32 + q;
    float4 v = *p;
    v.x = v.x * INVLN2 - ls;
    v.y = v.y * INVLN2 - ls;
    v.z = v.z * INVLN2 - ls;
    v.w = v.w * INVLN2 - ls;
    *p = v;
}

// ---------------- kernel 5: CTC forward DP — log2 domain, register trapezoid ----------------
__global__ __launch_bounds__(256)
void ctc_dp_kernel(const int* __restrict__ ys, const int* __restrict__ elens,
                   const int* __restrict__ ylens, float* __restrict__ out) {
    const int b    = blockIdx.x;
    const int tid  = threadIdx.x;
    const int lane = tid & 31;
    const int w    = tid >> 5;              // 0..7
    const int s    = w * 26 + lane - 6;     // state (may be <0 or >200 = halo/garbage)

    __shared__ float Asd[2][202];
    __shared__ float qbuf[2][24][128];      // 24 staged frames of lp2, double buffered

    const int ylen = ylens[b];
    const int tend = elens[b] - 1;

    const bool in_s  = (s >= 0 && s <= 200);
    const bool valid = in_s && (s <= 2 * ylen);
    const int  sc    = (s < 0) ? 0 : ((s > 200) ? 200 : s);
    const int  li    = (sc & 1) ? ((sc >> 1) + 1) : 0;
    bool skipf = false;
    if (valid && (s & 1) && s >= 3)
        skipf = (ys[b * LL + (s >> 1)] != ys[b * LL + (s >> 1) - 1]);

    float a = NEG_INF;
    if (valid && s < 2) a = g_lab[(size_t)(b * TT) * 128 + li];

    auto stage = [&](int cc, int bf) {
        int t0 = 1 + cc * 24;
        const float4* src = (const float4*)(g_lab + (size_t)(b * TT + t0) * 128);
        unsigned dst = smem_u32(&qbuf[bf][0][0]);
#pragma unroll
        for (int i = 0; i < 3; i++) {
            int idx = tid + 256 * i;
            CP_ASYNC16(dst + (unsigned)idx * 16u, src + idx);
        }
        CP_COMMIT();
    };

    stage(0, 0);
    stage(1, 1);

    int wb = 0, lastwb = 0;
    int t = 1, c = 0;
    while (t <= tend) {
        CP_WAIT1();
        __syncthreads();
        const int bf = c & 1;
        const int nfr = min(24, tend - t + 1);
        int fr = 0;
        while (fr < nfr) {
            const int jn = min(3, nfr - fr);
#pragma unroll 3
            for (int j = 0; j < jn; j++) {
                float a2 = __shfl_up_sync(0xffffffffu, a, 1);
                float a3 = __shfl_up_sync(0xffffffffu, a, 2);
                if (!skipf) a3 = NEG_INF;
                float lp = qbuf[bf][fr + j][li];
                float m  = fmaxf(a, fmaxf(a2, a3));
                float su = ex2f(a - m) + ex2f(a2 - m) + ex2f(a3 - m);
                float nv = m + lg2f(su) + lp;
                a = valid ? nv : NEG_INF;
            }
            if (lane >= 2 * jn && in_s) Asd[wb][s] = a;
            __syncthreads();
            a = in_s ? Asd[wb][s] : NEG_INF;
            lastwb = wb; wb ^= 1;
            fr += jn;
        }
        if (nfr == 24) stage(c + 2, bf);
        t += nfr; c++;
    }

    if (tid == 0) {
        float last = Asd[lastwb][2 * ylen];
        float prev = Asd[lastwb][2 * ylen - 1];
        float mm = fmaxf(last, prev);
        float l2v = mm + lg2f(ex2f(last - mm) + ex2f(prev - mm));
        float lnat = -l2v * LN2;
        if (!(lnat < -0.5f * NEG_INF)) lnat = 0.0f;   // zero_infinity
        atomicAdd(out, lnat * (1.0f / (float)BB));
    }
}

// ---------------- launch ----------------
extern "C" void kernel_launch(void* const* d_in, const int* in_sizes, int n_in,
                              void* d_out, int out_size) {
    const float* eouts = (const float*)d_in[0];
    const float* W     = (const float*)d_in[1];
    const float* bias  = (const float*)d_in[2];
    const int*   ys    = (const int*)d_in[3];
    const int*   elens = (const int*)d_in[4];
    const int*   ylens = (const int*)d_in[5];
    float* out = (float*)d_out;

    prep_kernel<<<2048, 256>>>(eouts, W, bias, ys, out, out_size);
    gemm8_kernel<<<dim3(250, 16), 256>>>(bias);
    gemm_label_kernel<<<256, 256>>>();
    fixup_kernel<<<(MROWS * 26 + 255) / 256, 256>>>();
    ctc_dp_kernel<<<BB, 256>>>(ys, elens, ylens, out);
}

// round 8
// speedup vs baseline: 1.9449x; 1.1000x over previous
#include <cuda_runtime.h>
#include <cuda_bf16.h>
#include <cstdint>

#define NEG_INF (-1e10f)
#define INVLN2 1.4426950408889634f
#define LN2    0.6931471805599453f

// Problem constants
#define BB 32
#define TT 1000
#define HH 512
#define VV 2048
#define LL 100
#define SS 201
#define MROWS (BB*TT)          // 32000
#define MPAD  (MROWS + 64)     // padding for DP prefetch overrun

// fp8 scaling: X*4, W*16 -> logits scaled by 64; descale in epilogue
#define XSCALE 4.0f
#define WSCALE 16.0f
#define DESCALE (1.0f / 64.0f)

// gemm8 v2 tiling
#define G8_ROW    40                    // u16 per SMEM row (32 data + 8 pad)
#define G8_TILE_B (128 * G8_ROW * 2)    // 10240 bytes per tile per buffer
#define G8_BUFS   4
#define G8_SMEM   (G8_BUFS * G8_TILE_B * 2)   // A + B rings = 81920 B

// ---------------- static device scratch (no allocation allowed) ----------------
__device__ __align__(16) static __nv_bfloat16 g_X[MROWS * HH];          // eouts bf16 (label gemm)
__device__ __align__(16) static unsigned short g_X8[MROWS * HH / 2];    // eouts e4m3 pairs (*4)
__device__ __align__(16) static unsigned short g_W8[VV * HH / 2];       // W e4m3 pairs (*16)
__device__ __align__(16) static __nv_bfloat16 g_Wlab[BB * 128 * HH];    // gathered label weights
__device__ __align__(16) static float         g_blab[BB * 128];         // gathered label bias
__device__ __align__(16) static float         g_sumexp[MPAD];           // per-row sum(exp(logit))
__device__ __align__(16) static float         g_lab[(size_t)MPAD * 128];// log2 softmax label probs

// ---------------- helpers ----------------
__device__ __forceinline__ unsigned smem_u32(const void* p) {
    return (unsigned)__cvta_generic_to_shared(p);
}

#define CP_ASYNC16(dst, src) \
    asm volatile("cp.async.ca.shared.global [%0], [%1], 16;\n" :: "r"(dst), "l"(src) : "memory")
#define CP_COMMIT() asm volatile("cp.async.commit_group;\n" ::: "memory")
#define CP_WAIT1()  asm volatile("cp.async.wait_group 1;\n" ::: "memory")
#define CP_WAIT2()  asm volatile("cp.async.wait_group 2;\n" ::: "memory")

__device__ __forceinline__ void ldmatrix_x4(unsigned* r, unsigned addr) {
    asm volatile("ldmatrix.sync.aligned.m8n8.x4.shared.b16 {%0,%1,%2,%3}, [%4];\n"
                 : "=r"(r[0]), "=r"(r[1]), "=r"(r[2]), "=r"(r[3]) : "r"(addr));
}

__device__ __forceinline__ void mma_bf16(float* d, const unsigned* a, unsigned b0, unsigned b1) {
    asm volatile("mma.sync.aligned.m16n8k16.row.col.f32.bf16.bf16.f32 "
                 "{%0,%1,%2,%3}, {%4,%5,%6,%7}, {%8,%9}, {%0,%1,%2,%3};\n"
                 : "+f"(d[0]), "+f"(d[1]), "+f"(d[2]), "+f"(d[3])
                 : "r"(a[0]), "r"(a[1]), "r"(a[2]), "r"(a[3]), "r"(b0), "r"(b1));
}

__device__ __forceinline__ void mma_fp8(float* d, const unsigned* a, unsigned b0, unsigned b1) {
    asm volatile("mma.sync.aligned.m16n8k32.row.col.f32.e4m3.e4m3.f32 "
                 "{%0,%1,%2,%3}, {%4,%5,%6,%7}, {%8,%9}, {%0,%1,%2,%3};\n"
                 : "+f"(d[0]), "+f"(d[1]), "+f"(d[2]), "+f"(d[3])
                 : "r"(a[0]), "r"(a[1]), "r"(a[2]), "r"(a[3]), "r"(b0), "r"(b1));
}

__device__ __forceinline__ float ex2f(float x) {
    float y; asm("ex2.approx.f32 %0, %1;" : "=f"(y) : "f"(x)); return y;
}
__device__ __forceinline__ float lg2f(float x) {
    float y; asm("lg2.approx.f32 %0, %1;" : "=f"(y) : "f"(x)); return y;
}

// pack two floats into e4m3x2 (lo = first elem, hi = second elem)
__device__ __forceinline__ unsigned short fp8pack(float lo, float hi) {
    unsigned short h;
    asm("cvt.rn.satfinite.e4m3x2.f32 %0, %1, %2;" : "=h"(h) : "f"(hi), "f"(lo));
    return h;
}

// ---------------- kernel 1: convert + gather + zero scratch/out ----------------
__global__ void prep_kernel(const float* __restrict__ eouts, const float* __restrict__ W,
                            const float* __restrict__ bias, const int* __restrict__ ys,
                            float* __restrict__ out, int out_size) {
    int i = blockIdx.x * blockDim.x + threadIdx.x;
    int stride = gridDim.x * blockDim.x;
    for (int k = i; k < MROWS * HH / 2; k += stride) {
        float2 v = ((const float2*)eouts)[k];
        g_X[2 * k]     = __float2bfloat16(v.x);
        g_X[2 * k + 1] = __float2bfloat16(v.y);
        g_X8[k] = fp8pack(v.x * XSCALE, v.y * XSCALE);
    }
    for (int k = i; k < VV * HH / 2; k += stride) {
        float2 v = ((const float2*)W)[k];
        g_W8[k] = fp8pack(v.x * WSCALE, v.y * WSCALE);
    }
    for (int k = i; k < BB * 128 * HH; k += stride) {
        int kk = k & (HH - 1);
        int j  = (k >> 9) & 127;
        int b  = k >> 16;
        int v  = (j == 0) ? 0 : ((j <= LL) ? ys[b * LL + (j - 1)] : -1);
        g_Wlab[k] = (v >= 0) ? __float2bfloat16(W[(size_t)v * HH + kk]) : __float2bfloat16(0.0f);
    }
    for (int k = i; k < BB * 128; k += stride) {
        int j = k & 127;
        int b = k >> 7;
        int v = (j == 0) ? 0 : ((j <= LL) ? ys[b * LL + (j - 1)] : -1);
        g_blab[k] = (v >= 0) ? bias[v] : 0.0f;
    }
    for (int k = i; k < MPAD; k += stride) g_sumexp[k] = 0.0f;
    for (int k = i; k < out_size; k += stride) out[k] = 0.0f;
}

// ---------------- kernel 2: fp8 full-V GEMM v2 (deep ring) + sumexp epilogue ----------------
// grid (250, 16): 128x128 logits tile, K=512 fp8 = 8 iterations of k=64.
// 4-buffer cp.async ring (dyn SMEM), prefetch distance 3, ONE barrier per iter.
__global__ __launch_bounds__(256)
void gemm8_kernel(const float* __restrict__ bias) {
    extern __shared__ unsigned short sm8[];
    const unsigned As0 = smem_u32(sm8);
    const unsigned Bs0 = As0 + G8_BUFS * G8_TILE_B;

    const int bx = blockIdx.x, by = blockIdx.y;
    const int tid = threadIdx.x, lane = tid & 31, wid = tid >> 5;
    const int wm = (wid & 3) * 32;
    const int wn = (wid >> 2) * 64;

    // staging: row = tid>>1 (0..127), 2 consecutive 16B chunks per thread
    const int ldrow = tid >> 1;
    const int ccol  = (tid & 1) * 16;       // u16 column of first chunk
    const unsigned short* Ag = g_X8 + (size_t)(bx * 128 + ldrow) * 256 + ccol;
    const unsigned short* Bg = g_W8 + (size_t)(by * 128 + ldrow) * 256 + ccol;
    const unsigned soff = (unsigned)(ldrow * G8_ROW + ccol) * 2;   // byte offset in tile

    auto stage = [&](int kt) {
        const unsigned bo = (unsigned)(kt & 3) * G8_TILE_B;
        const unsigned short* sa = Ag + kt * 32;
        const unsigned short* sb = Bg + kt * 32;
        CP_ASYNC16(As0 + bo + soff,      sa);
        CP_ASYNC16(As0 + bo + soff + 16, sa + 8);
        CP_ASYNC16(Bs0 + bo + soff,      sb);
        CP_ASYNC16(Bs0 + bo + soff + 16, sb + 8);
        CP_COMMIT();
    };

    float d[2][8][4];
#pragma unroll
    for (int mi = 0; mi < 2; mi++)
#pragma unroll
        for (int nj = 0; nj < 8; nj++)
#pragma unroll
            for (int q = 0; q < 4; q++) d[mi][nj][q] = 0.0f;

    // ldmatrix base addresses (buffer 0, kq 0)
    unsigned aAddr[2], bAddr[4];
#pragma unroll
    for (int mi = 0; mi < 2; mi++)
        aAddr[mi] = As0 + (unsigned)((wm + mi * 16 + (lane & 15)) * G8_ROW + (lane >> 4) * 8) * 2;
#pragma unroll
    for (int np = 0; np < 4; np++) {
        int r = wn + np * 16 + (lane & 7) + ((lane >> 4) & 1) * 8;
        int c = ((lane >> 3) & 1) * 8;
        bAddr[np] = Bs0 + (unsigned)(r * G8_ROW + c) * 2;
    }

    stage(0); stage(1); stage(2);

#pragma unroll
    for (int kt = 0; kt < 8; kt++) {
        CP_WAIT2();
        __syncthreads();
        const unsigned bo = (unsigned)(kt & 3) * G8_TILE_B;
#pragma unroll
        for (int kq = 0; kq < 2; kq++) {
            const unsigned off = bo + kq * 32;   // 16 u16 = 32 B per k-half
            unsigned ra[2][4], rb[4][4];
#pragma unroll
            for (int mi = 0; mi < 2; mi++) ldmatrix_x4(ra[mi], aAddr[mi] + off);
#pragma unroll
            for (int np = 0; np < 4; np++) ldmatrix_x4(rb[np], bAddr[np] + off);
#pragma unroll
            for (int mi = 0; mi < 2; mi++)
#pragma unroll
                for (int nj = 0; nj < 8; nj++) {
                    int np = nj >> 1;
                    unsigned b0 = (nj & 1) ? rb[np][2] : rb[np][0];
                    unsigned b1 = (nj & 1) ? rb[np][3] : rb[np][1];
                    mma_fp8(d[mi][nj], ra[mi], b0, b1);
                }
        }
        if (kt + 3 < 8) stage(kt + 3); else CP_COMMIT();
    }

    // epilogue: row sums of exp(logit) in log2 domain; descale fp8 product by 1/64
    const float dsc = INVLN2 * DESCALE;
#pragma unroll
    for (int mi = 0; mi < 2; mi++) {
        float se0 = 0.0f, se1 = 0.0f;
        int r = bx * 128 + wm + mi * 16 + (lane >> 2);
#pragma unroll
        for (int nj = 0; nj < 8; nj++) {
            int c = by * 128 + wn + nj * 8 + (lane & 3) * 2;
            float b0 = __ldg(&bias[c]) * INVLN2;
            float b1 = __ldg(&bias[c + 1]) * INVLN2;
            se0 += ex2f(fmaf(d[mi][nj][0], dsc, b0)) + ex2f(fmaf(d[mi][nj][1], dsc, b1));
            se1 += ex2f(fmaf(d[mi][nj][2], dsc, b0)) + ex2f(fmaf(d[mi][nj][3], dsc, b1));
        }
        se0 += __shfl_xor_sync(0xffffffffu, se0, 1);
        se0 += __shfl_xor_sync(0xffffffffu, se0, 2);
        se1 += __shfl_xor_sync(0xffffffffu, se1, 1);
        se1 += __shfl_xor_sync(0xffffffffu, se1, 2);
        if ((lane & 3) == 0) {
            atomicAdd(&g_sumexp[r], se0);
            atomicAdd(&g_sumexp[r + 8], se1);
        }
    }
}

// ---------------- kernel 3: label GEMM (bf16) + fused log-softmax epilogue ----------------
// grid 256: bx = blockIdx & 7 (M-tile of 128 frames), bb = blockIdx >> 3 (batch)
// epilogue writes lp2 = (logit + bias)/ln2 - log2(sumexp) directly (fixup fused).
__global__ __launch_bounds__(256)
void gemm_label_kernel() {
    __shared__ __nv_bfloat16 As[2][128 * 24];
    __shared__ __nv_bfloat16 Bs[2][128 * 24];

    const int bx = blockIdx.x & 7;
    const int bb = blockIdx.x >> 3;

    const int tid = threadIdx.x, lane = tid & 31, wid = tid >> 5;
    const int wm = (wid & 3) * 32;
    const int wn = (wid >> 2) * 64;

    const int ldrow = tid >> 1;
    const int ldcol = (tid & 1) * 8;

    int t = bx * 128 + ldrow;
    if (t > TT - 1) t = TT - 1;  // clamp (values unused)
    const __nv_bfloat16* Ag = g_X    + (size_t)(bb * TT + t) * HH + ldcol;
    const __nv_bfloat16* Bg = g_Wlab + (size_t)(bb * 128 + ldrow) * HH + ldcol;
    const int soff = ldrow * 24 + ldcol;

    float d[2][8][4];
#pragma unroll
    for (int mi = 0; mi < 2; mi++)
#pragma unroll
        for (int nj = 0; nj < 8; nj++)
#pragma unroll
            for (int q = 0; q < 4; q++) d[mi][nj][q] = 0.0f;

    unsigned aAddr[2], bAddr[4];
#pragma unroll
    for (int mi = 0; mi < 2; mi++)
        aAddr[mi] = smem_u32(&As[0][(wm + mi * 16 + (lane & 15)) * 24 + (lane >> 4) * 8]);
#pragma unroll
    for (int np = 0; np < 4; np++) {
        int r = wn + np * 16 + (lane & 7) + ((lane >> 4) & 1) * 8;
        int c = ((lane >> 3) & 1) * 8;
        bAddr[np] = smem_u32(&Bs[0][r * 24 + c]);
    }

    {
        CP_ASYNC16(smem_u32(&As[0][soff]), Ag + 0);
        CP_ASYNC16(smem_u32(&Bs[0][soff]), Bg + 0);
        CP_COMMIT();
        CP_ASYNC16(smem_u32(&As[1][soff]), Ag + 16);
        CP_ASYNC16(smem_u32(&Bs[1][soff]), Bg + 16);
        CP_COMMIT();
    }

    for (int kt = 0; kt < HH / 16; kt++) {
        CP_WAIT1();
        __syncthreads();
        const int buf = kt & 1;
        const unsigned off = buf * 6144u;

        unsigned ra[2][4], rb[4][4];
#pragma unroll
        for (int mi = 0; mi < 2; mi++) ldmatrix_x4(ra[mi], aAddr[mi] + off);
#pragma unroll
        for (int np = 0; np < 4; np++) ldmatrix_x4(rb[np], bAddr[np] + off);
        __syncthreads();

        if (kt + 2 < HH / 16) {
            int k0 = (kt + 2) * 16;
            CP_ASYNC16(smem_u32(&As[buf][soff]), Ag + k0);
            CP_ASYNC16(smem_u32(&Bs[buf][soff]), Bg + k0);
            CP_COMMIT();
        } else {
            CP_COMMIT();
        }

#pragma unroll
        for (int mi = 0; mi < 2; mi++)
#pragma unroll
            for (int nj = 0; nj < 8; nj++) {
                int np = nj >> 1;
                unsigned b0 = (nj & 1) ? rb[np][2] : rb[np][0];
                unsigned b1 = (nj & 1) ? rb[np][3] : rb[np][1];
                mma_bf16(d[mi][nj], ra[mi], b0, b1);
            }
    }

    // fused epilogue: lp2 = (logit + blab) * INVLN2 - log2(sumexp)
#pragma unroll
    for (int mi = 0; mi < 2; mi++) {
        int trow = bx * 128 + wm + mi * 16 + (lane >> 2);
        float ls0 = 0.0f, ls1 = 0.0f;
        if (trow < TT)     ls0 = lg2f(__ldg(&g_sumexp[bb * TT + trow]));
        if (trow + 8 < TT) ls1 = lg2f(__ldg(&g_sumexp[bb * TT + trow + 8]));
#pragma unroll
        for (int nj = 0; nj < 8; nj++) {
            int c = wn + nj * 8 + (lane & 3) * 2;
            float bl0 = g_blab[bb * 128 + c];
            float bl1 = g_blab[bb * 128 + c + 1];
            if (trow < TT) {
                float2 v = make_float2(fmaf(d[mi][nj][0] + bl0, INVLN2, -ls0),
                                       fmaf(d[mi][nj][1] + bl1, INVLN2, -ls0));
                *(float2*)&g_lab[(size_t)(bb * TT + trow) * 128 + c] = v;
            }
            if (trow + 8 < TT) {
                float2 v = make_float2(fmaf(d[mi][nj][2] + bl0, INVLN2, -ls1),
                                       fmaf(d[mi][nj][3] + bl1, INVLN2, -ls1));
                *(float2*)&g_lab[(size_t)(bb * TT + trow + 8) * 128 + c] = v;
            }
        }
    }
}

// ---------------- kernel 4: CTC forward DP — log2 domain, register trapezoid ----------------
__global__ __launch_bounds__(256)
void ctc_dp_kernel(const int* __restrict__ ys, const int* __restrict__ elens,
                   const int* __restrict__ ylens, float* __restrict__ out) {
    const int b    = blockIdx.x;
    const int tid  = threadIdx.x;
    const int lane = tid & 31;
    const int w    = tid >> 5;              // 0..7
    const int s    = w * 26 + lane - 6;     // state (may be <0 or >200 = halo/garbage)

    __shared__ float Asd[2][202];
    __shared__ float qbuf[2][24][128];      // 24 staged frames of lp2, double buffered

    const int ylen = ylens[b];
    const int tend = elens[b] - 1;

    const bool in_s  = (s >= 0 && s <= 200);
    const bool valid = in_s && (s <= 2 * ylen);
    const int  sc    = (s < 0) ? 0 : ((s > 200) ? 200 : s);
    const int  li    = (sc & 1) ? ((sc >> 1) + 1) : 0;
    bool skipf = false;
    if (valid && (s & 1) && s >= 3)
        skipf = (ys[b * LL + (s >> 1)] != ys[b * LL + (s >> 1) - 1]);

    float a = NEG_INF;
    if (valid && s < 2) a = g_lab[(size_t)(b * TT) * 128 + li];

    auto stage = [&](int cc, int bf) {
        int t0 = 1 + cc * 24;
        const float4* src = (const float4*)(g_lab + (size_t)(b * TT + t0) * 128);
        unsigned dst = smem_u32(&qbuf[bf][0][0]);
#pragma unroll
        for (int i = 0; i < 3; i++) {
            int idx = tid + 256 * i;
            CP_ASYNC16(dst + (unsigned)idx * 16u, src + idx);
        }
        CP_COMMIT();
    };

    stage(0, 0);
    stage(1, 1);

    int wb = 0, lastwb = 0;
    int t = 1, c = 0;
    while (t <= tend) {
        CP_WAIT1();
        __syncthreads();
        const int bf = c & 1;
        const int nfr = min(24, tend - t + 1);
        int fr = 0;
        while (fr < nfr) {
            const int jn = min(3, nfr - fr);
#pragma unroll 3
            for (int j = 0; j < jn; j++) {
                float a2 = __shfl_up_sync(0xffffffffu, a, 1);
                float a3 = __shfl_up_sync(0xffffffffu, a, 2);
                if (!skipf) a3 = NEG_INF;
                float lp = qbuf[bf][fr + j][li];
                float m  = fmaxf(a, fmaxf(a2, a3));
                float su = ex2f(a - m) + ex2f(a2 - m) + ex2f(a3 - m);
                float nv = m + lg2f(su) + lp;
                a = valid ? nv : NEG_INF;
            }
            if (lane >= 2 * jn && in_s) Asd[wb][s] = a;
            __syncthreads();
            a = in_s ? Asd[wb][s] : NEG_INF;
            lastwb = wb; wb ^= 1;
            fr += jn;
        }
        if (nfr == 24) stage(c + 2, bf);
        t += nfr; c++;
    }

    if (tid == 0) {
        float last = Asd[lastwb][2 * ylen];
        float prev = Asd[lastwb][2 * ylen - 1];
        float mm = fmaxf(last, prev);
        float l2v = mm + lg2f(ex2f(last - mm) + ex2f(prev - mm));
        float lnat = -l2v * LN2;
        if (!(lnat < -0.5f * NEG_INF)) lnat = 0.0f;   // zero_infinity
        atomicAdd(out, lnat * (1.0f / (float)BB));
    }
}

// ---------------- launch ----------------
extern "C" void kernel_launch(void* const* d_in, const int* in_sizes, int n_in,
                              void* d_out, int out_size) {
    const float* eouts = (const float*)d_in[0];
    const float* W     = (const float*)d_in[1];
    const float* bias  = (const float*)d_in[2];
    const int*   ys    = (const int*)d_in[3];
    const int*   elens = (const int*)d_in[4];
    const int*   ylens = (const int*)d_in[5];
    float* out = (float*)d_out;

    cudaFuncSetAttribute(gemm8_kernel,
                         cudaFuncAttributeMaxDynamicSharedMemorySize, G8_SMEM);

    prep_kernel<<<2048, 256>>>(eouts, W, bias, ys, out, out_size);
    gemm8_kernel<<<dim3(250, 16), 256, G8_SMEM>>>(bias);
    gemm_label_kernel<<<256, 256>>>();
    ctc_dp_kernel<<<BB, 256>>>(ys, elens, ylens, out);
}

// round 9
// speedup vs baseline: 2.1218x; 1.0910x over previous
#include <cuda_runtime.h>
#include <cuda_bf16.h>
#include <cstdint>

#define NEG_INF (-1e10f)
#define INVLN2 1.4426950408889634f
#define LN2    0.6931471805599453f

// Problem constants
#define BB 32
#define TT 1000
#define HH 512
#define VV 2048
#define LL 100
#define SS 201
#define MROWS (BB*TT)          // 32000
#define MPAD  (MROWS + 64)     // padding for DP prefetch overrun

// fp8 scaling: X*4, W*16 -> logits scaled by 64; descale in epilogue
#define XSCALE 4.0f
#define WSCALE 16.0f
#define DESCALE (1.0f / 64.0f)

// gemm8 tiling
#define G8_ROW    40                    // u16 per SMEM row (32 data + 8 pad)
#define G8_TILE_B (128 * G8_ROW * 2)    // 10240 bytes per tile per buffer
#define G8_BUFS   4
#define G8_SMEM   (G8_BUFS * G8_TILE_B * 2)   // A + B rings = 81920 B

// ---------------- static device scratch (no allocation allowed) ----------------
__device__ __align__(16) static unsigned short g_X8[MROWS * HH / 2];     // eouts e4m3 pairs (*4)
__device__ __align__(16) static unsigned short g_W8[VV * HH / 2];        // W e4m3 pairs (*16)
__device__ __align__(16) static unsigned short g_Wlab8[BB * 128 * HH / 2]; // gathered label W e4m3 (*16)
__device__ __align__(16) static float          g_blab[BB * 128];         // gathered label bias
__device__ __align__(16) static float          g_sumexp[MPAD];           // per-row sum(exp(logit))
__device__ __align__(16) static float          g_lab[(size_t)MPAD * 128];// log2 softmax label probs

// ---------------- helpers ----------------
__device__ __forceinline__ unsigned smem_u32(const void* p) {
    return (unsigned)__cvta_generic_to_shared(p);
}

#define CP_ASYNC16(dst, src) \
    asm volatile("cp.async.ca.shared.global [%0], [%1], 16;\n" :: "r"(dst), "l"(src) : "memory")
#define CP_COMMIT() asm volatile("cp.async.commit_group;\n" ::: "memory")
#define CP_WAIT1()  asm volatile("cp.async.wait_group 1;\n" ::: "memory")
#define CP_WAIT2()  asm volatile("cp.async.wait_group 2;\n" ::: "memory")

__device__ __forceinline__ void ldmatrix_x4(unsigned* r, unsigned addr) {
    asm volatile("ldmatrix.sync.aligned.m8n8.x4.shared.b16 {%0,%1,%2,%3}, [%4];\n"
                 : "=r"(r[0]), "=r"(r[1]), "=r"(r[2]), "=r"(r[3]) : "r"(addr));
}

__device__ __forceinline__ void mma_fp8(float* d, const unsigned* a, unsigned b0, unsigned b1) {
    asm volatile("mma.sync.aligned.m16n8k32.row.col.f32.e4m3.e4m3.f32 "
                 "{%0,%1,%2,%3}, {%4,%5,%6,%7}, {%8,%9}, {%0,%1,%2,%3};\n"
                 : "+f"(d[0]), "+f"(d[1]), "+f"(d[2]), "+f"(d[3])
                 : "r"(a[0]), "r"(a[1]), "r"(a[2]), "r"(a[3]), "r"(b0), "r"(b1));
}

__device__ __forceinline__ float ex2f(float x) {
    float y; asm("ex2.approx.f32 %0, %1;" : "=f"(y) : "f"(x)); return y;
}
__device__ __forceinline__ float lg2f(float x) {
    float y; asm("lg2.approx.f32 %0, %1;" : "=f"(y) : "f"(x)); return y;
}

// pack two floats into e4m3x2 (lo = first elem, hi = second elem)
__device__ __forceinline__ unsigned short fp8pack(float lo, float hi) {
    unsigned short h;
    asm("cvt.rn.satfinite.e4m3x2.f32 %0, %1, %2;" : "=h"(h) : "f"(hi), "f"(lo));
    return h;
}

// ---------------- kernel 1: convert + gather + zero scratch/out ----------------
__global__ void prep_kernel(const float* __restrict__ eouts, const float* __restrict__ W,
                            const float* __restrict__ bias, const int* __restrict__ ys,
                            float* __restrict__ out, int out_size) {
    int i = blockIdx.x * blockDim.x + threadIdx.x;
    int stride = gridDim.x * blockDim.x;
    for (int k = i; k < MROWS * HH / 2; k += stride) {
        float2 v = ((const float2*)eouts)[k];
        g_X8[k] = fp8pack(v.x * XSCALE, v.y * XSCALE);
    }
    for (int k = i; k < VV * HH / 2; k += stride) {
        float2 v = ((const float2*)W)[k];
        g_W8[k] = fp8pack(v.x * WSCALE, v.y * WSCALE);
    }
    for (int k = i; k < BB * 128 * HH / 2; k += stride) {
        int kk2 = k & 255;              // u16 (pair) index within row
        int j   = (k >> 8) & 127;
        int b   = k >> 15;
        int v   = (j == 0) ? 0 : ((j <= LL) ? ys[b * LL + (j - 1)] : -1);
        if (v >= 0) {
            float2 ww = ((const float2*)(W + (size_t)v * HH))[kk2];
            g_Wlab8[k] = fp8pack(ww.x * WSCALE, ww.y * WSCALE);
        } else {
            g_Wlab8[k] = 0;
        }
    }
    for (int k = i; k < BB * 128; k += stride) {
        int j = k & 127;
        int b = k >> 7;
        int v = (j == 0) ? 0 : ((j <= LL) ? ys[b * LL + (j - 1)] : -1);
        g_blab[k] = (v >= 0) ? bias[v] : 0.0f;
    }
    for (int k = i; k < MPAD; k += stride) g_sumexp[k] = 0.0f;
    for (int k = i; k < out_size; k += stride) out[k] = 0.0f;
}

// ---------------- kernel 2: fp8 GEMM, deep ring, templated epilogue ----------------
// MODE 0: grid (250,16) full-V tile; epilogue: sum(exp) rows -> atomicAdd g_sumexp
// MODE 1: grid (8,32)  label tile per batch; epilogue: lp2 -> g_lab (fused log-softmax)
template <int MODE>
__global__ __launch_bounds__(256)
void gemm8_kernel(const float* __restrict__ bias) {
    extern __shared__ unsigned short sm8[];
    const unsigned As0 = smem_u32(sm8);
    const unsigned Bs0 = As0 + G8_BUFS * G8_TILE_B;

    const int bx = blockIdx.x, by = blockIdx.y;
    const int tid = threadIdx.x, lane = tid & 31, wid = tid >> 5;
    const int wm = (wid & 3) * 32;
    const int wn = (wid >> 2) * 64;

    // staging: row = tid>>1 (0..127), 2 consecutive 16B chunks per thread
    const int ldrow = tid >> 1;
    const int ccol  = (tid & 1) * 16;       // u16 column of first chunk
    const unsigned short* Ag;
    const unsigned short* Bg;
    if (MODE == 0) {
        Ag = g_X8 + (size_t)(bx * 128 + ldrow) * 256 + ccol;
        Bg = g_W8 + (size_t)(by * 128 + ldrow) * 256 + ccol;
    } else {
        int t = bx * 128 + ldrow;
        if (t > TT - 1) t = TT - 1;         // clamp (values unused)
        Ag = g_X8    + (size_t)(by * TT + t) * 256 + ccol;
        Bg = g_Wlab8 + (size_t)(by * 128 + ldrow) * 256 + ccol;
    }
    const unsigned soff = (unsigned)(ldrow * G8_ROW + ccol) * 2;   // byte offset in tile

    auto stage = [&](int kt) {
        const unsigned bo = (unsigned)(kt & 3) * G8_TILE_B;
        const unsigned short* sa = Ag + kt * 32;
        const unsigned short* sb = Bg + kt * 32;
        CP_ASYNC16(As0 + bo + soff,      sa);
        CP_ASYNC16(As0 + bo + soff + 16, sa + 8);
        CP_ASYNC16(Bs0 + bo + soff,      sb);
        CP_ASYNC16(Bs0 + bo + soff + 16, sb + 8);
        CP_COMMIT();
    };

    float d[2][8][4];
#pragma unroll
    for (int mi = 0; mi < 2; mi++)
#pragma unroll
        for (int nj = 0; nj < 8; nj++)
#pragma unroll
            for (int q = 0; q < 4; q++) d[mi][nj][q] = 0.0f;

    unsigned aAddr[2], bAddr[4];
#pragma unroll
    for (int mi = 0; mi < 2; mi++)
        aAddr[mi] = As0 + (unsigned)((wm + mi * 16 + (lane & 15)) * G8_ROW + (lane >> 4) * 8) * 2;
#pragma unroll
    for (int np = 0; np < 4; np++) {
        int r = wn + np * 16 + (lane & 7) + ((lane >> 4) & 1) * 8;
        int c = ((lane >> 3) & 1) * 8;
        bAddr[np] = Bs0 + (unsigned)(r * G8_ROW + c) * 2;
    }

    stage(0); stage(1); stage(2);

#pragma unroll
    for (int kt = 0; kt < 8; kt++) {
        CP_WAIT2();
        __syncthreads();
        const unsigned bo = (unsigned)(kt & 3) * G8_TILE_B;
#pragma unroll
        for (int kq = 0; kq < 2; kq++) {
            const unsigned off = bo + kq * 32;
            unsigned ra[2][4], rb[4][4];
#pragma unroll
            for (int mi = 0; mi < 2; mi++) ldmatrix_x4(ra[mi], aAddr[mi] + off);
#pragma unroll
            for (int np = 0; np < 4; np++) ldmatrix_x4(rb[np], bAddr[np] + off);
#pragma unroll
            for (int mi = 0; mi < 2; mi++)
#pragma unroll
                for (int nj = 0; nj < 8; nj++) {
                    int np = nj >> 1;
                    unsigned b0 = (nj & 1) ? rb[np][2] : rb[np][0];
                    unsigned b1 = (nj & 1) ? rb[np][3] : rb[np][1];
                    mma_fp8(d[mi][nj], ra[mi], b0, b1);
                }
        }
        if (kt + 3 < 8) stage(kt + 3); else CP_COMMIT();
    }

    if (MODE == 0) {
        // row sums of exp(logit) in log2 domain; descale fp8 product by 1/64
        const float dsc = INVLN2 * DESCALE;
#pragma unroll
        for (int mi = 0; mi < 2; mi++) {
            float se0 = 0.0f, se1 = 0.0f;
            int r = bx * 128 + wm + mi * 16 + (lane >> 2);
#pragma unroll
            for (int nj = 0; nj < 8; nj++) {
                int c = by * 128 + wn + nj * 8 + (lane & 3) * 2;
                float b0 = __ldg(&bias[c]) * INVLN2;
                float b1 = __ldg(&bias[c + 1]) * INVLN2;
                se0 += ex2f(fmaf(d[mi][nj][0], dsc, b0)) + ex2f(fmaf(d[mi][nj][1], dsc, b1));
                se1 += ex2f(fmaf(d[mi][nj][2], dsc, b0)) + ex2f(fmaf(d[mi][nj][3], dsc, b1));
            }
            se0 += __shfl_xor_sync(0xffffffffu, se0, 1);
            se0 += __shfl_xor_sync(0xffffffffu, se0, 2);
            se1 += __shfl_xor_sync(0xffffffffu, se1, 1);
            se1 += __shfl_xor_sync(0xffffffffu, se1, 2);
            if ((lane & 3) == 0) {
                atomicAdd(&g_sumexp[r], se0);
                atomicAdd(&g_sumexp[r + 8], se1);
            }
        }
    } else {
        // fused log-softmax: lp2 = (d/64 + blab)/ln2 - log2(sumexp)
#pragma unroll
        for (int mi = 0; mi < 2; mi++) {
            int trow = bx * 128 + wm + mi * 16 + (lane >> 2);
            float ls0 = 0.0f, ls1 = 0.0f;
            if (trow < TT)     ls0 = lg2f(__ldg(&g_sumexp[by * TT + trow]));
            if (trow + 8 < TT) ls1 = lg2f(__ldg(&g_sumexp[by * TT + trow + 8]));
#pragma unroll
            for (int nj = 0; nj < 8; nj++) {
                int c = wn + nj * 8 + (lane & 3) * 2;
                float bl0 = g_blab[by * 128 + c];
                float bl1 = g_blab[by * 128 + c + 1];
                if (trow < TT) {
                    float2 v = make_float2(
                        fmaf(fmaf(d[mi][nj][0], DESCALE, bl0), INVLN2, -ls0),
                        fmaf(fmaf(d[mi][nj][1], DESCALE, bl1), INVLN2, -ls0));
                    *(float2*)&g_lab[(size_t)(by * TT + trow) * 128 + c] = v;
                }
                if (trow + 8 < TT) {
                    float2 v = make_float2(
                        fmaf(fmaf(d[mi][nj][2], DESCALE, bl0), INVLN2, -ls1),
                        fmaf(fmaf(d[mi][nj][3], DESCALE, bl1), INVLN2, -ls1));
                    *(float2*)&g_lab[(size_t)(by * TT + trow + 8) * 128 + c] = v;
                }
            }
        }
    }
}

// ---------------- kernel 3: CTC forward DP — fused double-step trapezoid ----------------
// 9 warps (288 thr); warp w holds states s = 24w + lane - 8 (halo 8).
// Two fused 2-frame steps per barrier group (4 frames / commit).
__global__ __launch_bounds__(288)
void ctc_dp_kernel(const int* __restrict__ ys, const int* __restrict__ elens,
                   const int* __restrict__ ylens, float* __restrict__ out) {
    const int b    = blockIdx.x;
    const int tid  = threadIdx.x;
    const int lane = tid & 31;
    const int w    = tid >> 5;              // 0..8
    const int s    = w * 24 + lane - 8;     // -8..215

    __shared__ float Asd[2][204];
    __shared__ float qbuf[2][24][128];

    const int ylen = ylens[b];
    const int tend = elens[b] - 1;

    const bool in_s  = (s >= 0 && s <= 200);
    const bool valid = in_s && (s <= 2 * ylen);

    const int sc0 = min(max(s, 0), 200);
    const int li0 = (sc0 & 1) ? ((sc0 >> 1) + 1) : 0;

    auto skip_of = [&](int x) -> float {
        if ((x & 1) && x >= 3 && x <= 200) {
            int h = x >> 1;
            return (ys[b * LL + h] != ys[b * LL + h - 1]) ? 1.0f : 0.0f;
        }
        return 0.0f;
    };
    const float sk0 = skip_of(s);
    const float sk1 = skip_of(s - 1);
    const float sk2 = skip_of(s - 2);
    const bool use3 = (sk0 != 0.0f) || (sk1 != 0.0f);   // a[s-3] reachable in 2 steps
    const bool use4 = (sk0 != 0.0f) && (sk2 != 0.0f);   // a[s-4] reachable in 2 steps

    // t = 0 init
    float a = NEG_INF;
    if (valid && s < 2) a = g_lab[(size_t)(b * TT) * 128 + li0];

    auto stage = [&](int cc, int bf) {
        int t0 = 1 + cc * 24;
        const float4* src = (const float4*)(g_lab + (size_t)(b * TT + t0) * 128);
        unsigned dst = smem_u32(&qbuf[bf][0][0]);
        for (int idx = tid; idx < 768; idx += 288)
            CP_ASYNC16(dst + (unsigned)idx * 16u, src + idx);
        CP_COMMIT();
    };

    // fused two-frame step: frames f0 (lp_t) and f0+1 (lp_{t+1})
    auto dstep = [&](int f0, int bf) {
        float a1 = __shfl_up_sync(0xffffffffu, a, 1);
        float a2 = __shfl_up_sync(0xffffffffu, a, 2);
        float a3 = __shfl_up_sync(0xffffffffu, a, 3);
        float a4 = __shfl_up_sync(0xffffffffu, a, 4);
        float a3u = use3 ? a3 : NEG_INF;
        float a4u = use4 ? a4 : NEG_INF;
        float lpA = qbuf[bf][f0][li0];
        float lpB = qbuf[bf][f0 + 1][li0];
        float P0 = ex2f(lpA);
        float P1 = __shfl_up_sync(0xffffffffu, P0, 1);
        float P2 = __shfl_up_sync(0xffffffffu, P0, 2);
        float m  = fmaxf(fmaxf(a, a1), fmaxf(fmaxf(a2, a3u), a4u));
        float q0 = ex2f(a - m),  q1 = ex2f(a1 - m), q2 = ex2f(a2 - m);
        float q3 = ex2f(a3u - m), q4 = ex2f(a4u - m);
        float I0 = fmaf(sk0, q2, q0 + q1);
        float I1 = fmaf(sk1, q3, q1 + q2);
        float I2 = fmaf(sk2, q4, q2 + q3);
        float S  = fmaf(P0, I0, fmaf(P1, I1, sk0 * P2 * I2));
        float nv = fmaxf(m + lg2f(S) + lpB, NEG_INF);
        a = valid ? nv : NEG_INF;
    };

    auto sstep = [&](int f0, int bf) {
        float a1 = __shfl_up_sync(0xffffffffu, a, 1);
        float a2 = __shfl_up_sync(0xffffffffu, a, 2);
        if (sk0 == 0.0f) a2 = NEG_INF;
        float lp = qbuf[bf][f0][li0];
        float m  = fmaxf(a, fmaxf(a1, a2));
        float su = ex2f(a - m) + ex2f(a1 - m) + ex2f(a2 - m);
        float nv = fmaxf(m + lg2f(su) + lp, NEG_INF);
        a = valid ? nv : NEG_INF;
    };

    stage(0, 0);
    stage(1, 1);

    int wb = 0, lastwb = 0;
    int t = 1, c = 0;
    while (t <= tend) {
        CP_WAIT1();
        __syncthreads();
        const int bf = c & 1;
        const int nfr = min(24, tend - t + 1);
        int fr = 0;
        while (fr < nfr) {
            int rem = nfr - fr;
            int h;
            if (rem >= 4)      { dstep(fr, bf); dstep(fr + 2, bf); h = 8; fr += 4; }
            else if (rem >= 2) { dstep(fr, bf);                    h = 4; fr += 2; }
            else               { sstep(fr, bf);                    h = 2; fr += 1; }
            if (lane >= h && in_s) Asd[wb][s] = a;   // overlapping commits bit-identical
            __syncthreads();
            a = in_s ? Asd[wb][s] : NEG_INF;
            lastwb = wb; wb ^= 1;
        }
        if (nfr == 24) stage(c + 2, bf);
        t += nfr; c++;
    }

    if (tid == 0) {
        float last = Asd[lastwb][2 * ylen];
        float prev = Asd[lastwb][2 * ylen - 1];
        float mm = fmaxf(last, prev);
        float l2v = mm + lg2f(ex2f(last - mm) + ex2f(prev - mm));
        float lnat = -l2v * LN2;
        if (!(lnat < -0.5f * NEG_INF)) lnat = 0.0f;   // zero_infinity
        atomicAdd(out, lnat * (1.0f / (float)BB));
    }
}

// ---------------- launch ----------------
extern "C" void kernel_launch(void* const* d_in, const int* in_sizes, int n_in,
                              void* d_out, int out_size) {
    const float* eouts = (const float*)d_in[0];
    const float* W     = (const float*)d_in[1];
    const float* bias  = (const float*)d_in[2];
    const int*   ys    = (const int*)d_in[3];
    const int*   elens = (const int*)d_in[4];
    const int*   ylens = (const int*)d_in[5];
    float* out = (float*)d_out;

    cudaFuncSetAttribute(gemm8_kernel<0>,
                         cudaFuncAttributeMaxDynamicSharedMemorySize, G8_SMEM);
    cudaFuncSetAttribute(gemm8_kernel<1>,
                         cudaFuncAttributeMaxDynamicSharedMemorySize, G8_SMEM);

    prep_kernel<<<2048, 256>>>(eouts, W, bias, ys, out, out_size);
    gemm8_kernel<0><<<dim3(250, 16), 256, G8_SMEM>>>(bias);
    gemm8_kernel<1><<<dim3(8, 32), 256, G8_SMEM>>>(bias);
    ctc_dp_kernel<<<BB, 288>>>(ys, elens, ylens, out);
}